// round 1
// baseline (speedup 1.0000x reference)
#include <cuda_runtime.h>
#include <cstdint>

// ---------------------------------------------------------------------------
// MultiAttnLayer: block-local attention transformer layer, tf32 mma.sync path.
//   src(4,8192,1024) -> out(4,8192,1024)
// Pipeline:
//   1. qkv   = src @ in_proj_w^T + in_proj_b            (GEMM 32768x3072x1024)
//   2. ctx   = window-local MHA(qkv)                    (4096 blocks of 128x128x64 x2)
//   3. tmp   = ctx @ out_proj_w^T + out_proj_b          (GEMM 32768x1024x1024)
//   4. h     = LN(src + tmp)
//   5. ff    = relu(h @ w1^T + b1)                      (GEMM 32768x4096x1024)
//   6. tmp   = ff @ w2^T + b2                           (GEMM 32768x1024x4096)
//   7. out   = LN(h + tmp)
// ---------------------------------------------------------------------------

constexpr int BB   = 4;
constexpr int SEQ  = 8192;
constexpr int DM   = 1024;
constexpr int NH   = 16;
constexpr int HD   = 64;
constexpr int WIN  = 128;
constexpr int NWIN = SEQ / WIN;   // 64
constexpr int FF   = 4096;
constexpr int T    = BB * SEQ;    // 32768 tokens
constexpr float LN_EPS = 1e-5f;

// Scratch (static device globals: allocation-free).
__device__ float g_qkv[(size_t)T * 3 * DM];  // 402 MB
__device__ float g_ctx[(size_t)T * DM];      // 128 MB
__device__ float g_tmp[(size_t)T * DM];      // 128 MB
__device__ float g_h  [(size_t)T * DM];      // 128 MB
__device__ float g_ff [(size_t)T * FF];      // 512 MB

__device__ __forceinline__ float f2tf32(float x) {
    uint32_t u;
    asm("cvt.rna.tf32.f32 %0, %1;" : "=r"(u) : "f"(x));
    return __uint_as_float(u);
}

__device__ __forceinline__ void mma_tf32(float c[4],
                                         uint32_t a0, uint32_t a1, uint32_t a2, uint32_t a3,
                                         uint32_t b0, uint32_t b1) {
    asm volatile(
        "mma.sync.aligned.m16n8k8.row.col.f32.tf32.tf32.f32 "
        "{%0,%1,%2,%3}, {%4,%5,%6,%7}, {%8,%9}, {%0,%1,%2,%3};\n"
        : "+f"(c[0]), "+f"(c[1]), "+f"(c[2]), "+f"(c[3])
        : "r"(a0), "r"(a1), "r"(a2), "r"(a3), "r"(b0), "r"(b1));
}

// ---------------------------------------------------------------------------
// GEMM: C[M,N] = A[M,K] @ B[N,K]^T + bias[N]   (all row-major, dims % 128 == 0,
// K % 32 == 0). EPI: 0 = bias only, 1 = bias + relu.
// Block tile 128x128, BK=32, 256 threads (8 warps as 4m x 2n, warp tile 32x64).
// ---------------------------------------------------------------------------
template <int EPI>
__global__ __launch_bounds__(256)
void gemm_tf32(const float* __restrict__ A, const float* __restrict__ Bw,
               const float* __restrict__ bias, float* __restrict__ C,
               int M, int N, int K)
{
    constexpr int BM = 128, BN = 128, BK = 32, LDA = BK + 1;  // pad -> conflict-free
    __shared__ float As[BM * LDA];
    __shared__ float Bs[BN * LDA];

    const int tid  = threadIdx.x;
    const int wid  = tid >> 5;
    const int lane = tid & 31;
    const int gid  = lane >> 2;      // 0..7
    const int tig  = lane & 3;       // 0..3
    const int wm   = wid >> 1;       // 0..3
    const int wn   = wid & 1;        // 0..1
    const int bm   = blockIdx.y * BM;
    const int bn   = blockIdx.x * BN;

    float acc[2][8][4];
#pragma unroll
    for (int i = 0; i < 2; i++)
#pragma unroll
        for (int j = 0; j < 8; j++)
#pragma unroll
            for (int l = 0; l < 4; l++) acc[i][j][l] = 0.f;

    for (int k0 = 0; k0 < K; k0 += BK) {
        // Load tiles (128 rows x 32 cols each), tf32-rounded.
#pragma unroll
        for (int f = 0; f < 4; f++) {
            int id = tid + f * 256;          // 0..1023 float4 slots
            int r  = id >> 3;
            int c4 = (id & 7) * 4;
            float4 va = *(const float4*)(A  + (size_t)(bm + r) * K + k0 + c4);
            float4 vb = *(const float4*)(Bw + (size_t)(bn + r) * K + k0 + c4);
            As[r * LDA + c4 + 0] = f2tf32(va.x);
            As[r * LDA + c4 + 1] = f2tf32(va.y);
            As[r * LDA + c4 + 2] = f2tf32(va.z);
            As[r * LDA + c4 + 3] = f2tf32(va.w);
            Bs[r * LDA + c4 + 0] = f2tf32(vb.x);
            Bs[r * LDA + c4 + 1] = f2tf32(vb.y);
            Bs[r * LDA + c4 + 2] = f2tf32(vb.z);
            Bs[r * LDA + c4 + 3] = f2tf32(vb.w);
        }
        __syncthreads();

#pragma unroll
        for (int ks = 0; ks < 4; ks++) {
            const int kk = ks * 8;
            uint32_t a[2][4];
#pragma unroll
            for (int im = 0; im < 2; im++) {
                const int mb = wm * 32 + im * 16;
                a[im][0] = __float_as_uint(As[(mb + gid    ) * LDA + kk + tig    ]);
                a[im][1] = __float_as_uint(As[(mb + 8 + gid) * LDA + kk + tig    ]);
                a[im][2] = __float_as_uint(As[(mb + gid    ) * LDA + kk + tig + 4]);
                a[im][3] = __float_as_uint(As[(mb + 8 + gid) * LDA + kk + tig + 4]);
            }
#pragma unroll
            for (int in = 0; in < 8; in++) {
                const int nb = wn * 64 + in * 8;
                uint32_t b0 = __float_as_uint(Bs[(nb + gid) * LDA + kk + tig    ]);
                uint32_t b1 = __float_as_uint(Bs[(nb + gid) * LDA + kk + tig + 4]);
                mma_tf32(acc[0][in], a[0][0], a[0][1], a[0][2], a[0][3], b0, b1);
                mma_tf32(acc[1][in], a[1][0], a[1][1], a[1][2], a[1][3], b0, b1);
            }
        }
        __syncthreads();
    }

    // Epilogue
#pragma unroll
    for (int im = 0; im < 2; im++) {
#pragma unroll
        for (int in = 0; in < 8; in++) {
            const int r0 = bm + wm * 32 + im * 16 + gid;
            const int c0 = bn + wn * 64 + in * 8 + tig * 2;
            const float bv0 = bias[c0], bv1 = bias[c0 + 1];
            float v00 = acc[im][in][0] + bv0;
            float v01 = acc[im][in][1] + bv1;
            float v10 = acc[im][in][2] + bv0;
            float v11 = acc[im][in][3] + bv1;
            if (EPI == 1) {
                v00 = fmaxf(v00, 0.f); v01 = fmaxf(v01, 0.f);
                v10 = fmaxf(v10, 0.f); v11 = fmaxf(v11, 0.f);
            }
            C[(size_t)r0 * N + c0]           = v00;
            C[(size_t)r0 * N + c0 + 1]       = v01;
            C[(size_t)(r0 + 8) * N + c0]     = v10;
            C[(size_t)(r0 + 8) * N + c0 + 1] = v11;
        }
    }
}

// ---------------------------------------------------------------------------
// Window-local attention: one block per (head, window, batch).
// Q,K,V: 128x64.  scores = Q K^T * 0.125 -> softmax -> ctx = P V.
// 256 threads = 8 warps; warp w owns rows [16w, 16w+16).
// ---------------------------------------------------------------------------
constexpr int QK_LD = HD + 4;     // 68   (pad: stride%32 == 4 -> conflict-free frags)
constexpr int S_LD  = WIN + 4;    // 132
constexpr int ATTN_SMEM_FLOATS = 2 * WIN * QK_LD + WIN * S_LD + HD * S_LD;
constexpr int ATTN_SMEM_BYTES  = ATTN_SMEM_FLOATS * 4;   // 171,008 B

__global__ __launch_bounds__(256)
void attn_kernel()
{
    extern __shared__ float sm[];
    float* Qs = sm;                      // [128][68]
    float* Ks = Qs + WIN * QK_LD;        // [128][68]   (B operand: [n=key][k=dim])
    float* Ss = Ks + WIN * QK_LD;        // [128][132]  scores / probs
    float* Vt = Ss + WIN * S_LD;         // [64][132]   V transposed: [n=dim][k=key]

    const int h  = blockIdx.x;
    const int w  = blockIdx.y;
    const int b  = blockIdx.z;
    const int t0 = b * SEQ + w * WIN;

    const int tid  = threadIdx.x;
    const int wid  = tid >> 5;
    const int lane = tid & 31;
    const int gid  = lane >> 2;
    const int tig  = lane & 3;

    const int qoff = h * HD;
    const int koff = DM + h * HD;
    const int voff = 2 * DM + h * HD;

    // Load Q, K (row-major) and V (transposed), tf32-rounded.
#pragma unroll
    for (int f = 0; f < 8; f++) {
        int id = tid + f * 256;          // 0..2047 float4 slots (128 rows x 16)
        int r  = id >> 4;
        int c4 = (id & 15) * 4;
        const float* base = g_qkv + (size_t)(t0 + r) * (3 * DM);
        float4 vq = *(const float4*)(base + qoff + c4);
        float4 vk = *(const float4*)(base + koff + c4);
        float4 vv = *(const float4*)(base + voff + c4);
        Qs[r * QK_LD + c4 + 0] = f2tf32(vq.x);
        Qs[r * QK_LD + c4 + 1] = f2tf32(vq.y);
        Qs[r * QK_LD + c4 + 2] = f2tf32(vq.z);
        Qs[r * QK_LD + c4 + 3] = f2tf32(vq.w);
        Ks[r * QK_LD + c4 + 0] = f2tf32(vk.x);
        Ks[r * QK_LD + c4 + 1] = f2tf32(vk.y);
        Ks[r * QK_LD + c4 + 2] = f2tf32(vk.z);
        Ks[r * QK_LD + c4 + 3] = f2tf32(vk.w);
        Vt[(c4 + 0) * S_LD + r] = f2tf32(vv.x);
        Vt[(c4 + 1) * S_LD + r] = f2tf32(vv.y);
        Vt[(c4 + 2) * S_LD + r] = f2tf32(vv.z);
        Vt[(c4 + 3) * S_LD + r] = f2tf32(vv.w);
    }
    __syncthreads();

    const int m0 = wid * 16;

    // scores = Q @ K^T : per warp 16x128, K-dim 64.
    float sc[16][4];
#pragma unroll
    for (int n = 0; n < 16; n++)
#pragma unroll
        for (int l = 0; l < 4; l++) sc[n][l] = 0.f;

#pragma unroll
    for (int ks = 0; ks < 8; ks++) {
        const int kk = ks * 8;
        uint32_t a0 = __float_as_uint(Qs[(m0 + gid    ) * QK_LD + kk + tig    ]);
        uint32_t a1 = __float_as_uint(Qs[(m0 + 8 + gid) * QK_LD + kk + tig    ]);
        uint32_t a2 = __float_as_uint(Qs[(m0 + gid    ) * QK_LD + kk + tig + 4]);
        uint32_t a3 = __float_as_uint(Qs[(m0 + 8 + gid) * QK_LD + kk + tig + 4]);
#pragma unroll
        for (int n = 0; n < 16; n++) {
            uint32_t b0 = __float_as_uint(Ks[(n * 8 + gid) * QK_LD + kk + tig    ]);
            uint32_t b1 = __float_as_uint(Ks[(n * 8 + gid) * QK_LD + kk + tig + 4]);
            mma_tf32(sc[n], a0, a1, a2, a3, b0, b1);
        }
    }

    const float scale = 0.125f;   // 1/sqrt(64)
#pragma unroll
    for (int n = 0; n < 16; n++) {
        const int r = m0 + gid;
        const int c = n * 8 + tig * 2;
        Ss[r * S_LD + c]           = sc[n][0] * scale;
        Ss[r * S_LD + c + 1]       = sc[n][1] * scale;
        Ss[(r + 8) * S_LD + c]     = sc[n][2] * scale;
        Ss[(r + 8) * S_LD + c + 1] = sc[n][3] * scale;
    }
    __syncthreads();

    // Softmax: one row per thread (threads 0..127).
    if (tid < WIN) {
        float* row = Ss + tid * S_LD;
        float m = -1e30f;
#pragma unroll 4
        for (int i = 0; i < WIN; i++) m = fmaxf(m, row[i]);
        float s = 0.f;
#pragma unroll 4
        for (int i = 0; i < WIN; i++) { float e = __expf(row[i] - m); row[i] = e; s += e; }
        const float inv = 1.f / s;
#pragma unroll 4
        for (int i = 0; i < WIN; i++) row[i] = f2tf32(row[i] * inv);
    }
    __syncthreads();

    // ctx = P @ V : per warp 16x64, K-dim 128.  B operand = Vt[n=dim][k=key].
    float o[8][4];
#pragma unroll
    for (int n = 0; n < 8; n++)
#pragma unroll
        for (int l = 0; l < 4; l++) o[n][l] = 0.f;

#pragma unroll
    for (int ks = 0; ks < 16; ks++) {
        const int kk = ks * 8;
        uint32_t a0 = __float_as_uint(Ss[(m0 + gid    ) * S_LD + kk + tig    ]);
        uint32_t a1 = __float_as_uint(Ss[(m0 + 8 + gid) * S_LD + kk + tig    ]);
        uint32_t a2 = __float_as_uint(Ss[(m0 + gid    ) * S_LD + kk + tig + 4]);
        uint32_t a3 = __float_as_uint(Ss[(m0 + 8 + gid) * S_LD + kk + tig + 4]);
#pragma unroll
        for (int n = 0; n < 8; n++) {
            uint32_t b0 = __float_as_uint(Vt[(n * 8 + gid) * S_LD + kk + tig    ]);
            uint32_t b1 = __float_as_uint(Vt[(n * 8 + gid) * S_LD + kk + tig + 4]);
            mma_tf32(o[n], a0, a1, a2, a3, b0, b1);
        }
    }

#pragma unroll
    for (int n = 0; n < 8; n++) {
        const int r = m0 + gid;
        const int c = n * 8 + tig * 2;
        float* o0 = g_ctx + (size_t)(t0 + r) * DM + h * HD + c;
        float* o1 = g_ctx + (size_t)(t0 + r + 8) * DM + h * HD + c;
        o0[0] = o[n][0]; o0[1] = o[n][1];
        o1[0] = o[n][2]; o1[1] = o[n][3];
    }
}

// ---------------------------------------------------------------------------
// out = LayerNorm(A + B) * g + beta  — one block (256 thr) per token, D=1024.
// ---------------------------------------------------------------------------
__global__ __launch_bounds__(256)
void add_ln_kernel(const float* __restrict__ A, const float* __restrict__ Bq,
                   const float* __restrict__ gam, const float* __restrict__ bet,
                   float* __restrict__ out)
{
    const int t    = blockIdx.x;
    const int tid  = threadIdx.x;
    const int lane = tid & 31;
    const int wid  = tid >> 5;

    const size_t base = (size_t)t * DM + tid * 4;
    float4 a  = *(const float4*)(A  + base);
    float4 bb = *(const float4*)(Bq + base);
    float x0 = a.x + bb.x, x1 = a.y + bb.y, x2 = a.z + bb.z, x3 = a.w + bb.w;

    float s = x0 + x1 + x2 + x3;
    float q = x0 * x0 + x1 * x1 + x2 * x2 + x3 * x3;
#pragma unroll
    for (int o = 16; o > 0; o >>= 1) {
        s += __shfl_xor_sync(0xffffffffu, s, o);
        q += __shfl_xor_sync(0xffffffffu, q, o);
    }
    __shared__ float rs[8], rq[8];
    if (lane == 0) { rs[wid] = s; rq[wid] = q; }
    __syncthreads();
    if (wid == 0) {
        s = (lane < 8) ? rs[lane] : 0.f;
        q = (lane < 8) ? rq[lane] : 0.f;
#pragma unroll
        for (int o = 4; o > 0; o >>= 1) {
            s += __shfl_xor_sync(0xffffffffu, s, o);
            q += __shfl_xor_sync(0xffffffffu, q, o);
        }
        if (lane == 0) { rs[0] = s; rq[0] = q; }
    }
    __syncthreads();
    const float mu   = rs[0] * (1.f / DM);
    const float var  = rq[0] * (1.f / DM) - mu * mu;
    const float rstd = rsqrtf(var + LN_EPS);

    float4 gv = *(const float4*)(gam + tid * 4);
    float4 bv = *(const float4*)(bet + tid * 4);
    float4 r;
    r.x = (x0 - mu) * rstd * gv.x + bv.x;
    r.y = (x1 - mu) * rstd * gv.y + bv.y;
    r.z = (x2 - mu) * rstd * gv.z + bv.z;
    r.w = (x3 - mu) * rstd * gv.w + bv.w;
    *(float4*)(out + base) = r;
}

// ---------------------------------------------------------------------------
extern "C" void kernel_launch(void* const* d_in, const int* in_sizes, int n_in,
                              void* d_out, int out_size)
{
    const float* src   = (const float*)d_in[0];
    const float* in_w  = (const float*)d_in[1];
    const float* in_b  = (const float*)d_in[2];
    const float* ow    = (const float*)d_in[3];
    const float* ob    = (const float*)d_in[4];
    const float* w1    = (const float*)d_in[5];
    const float* b1    = (const float*)d_in[6];
    const float* w2    = (const float*)d_in[7];
    const float* b2    = (const float*)d_in[8];
    const float* ln1g  = (const float*)d_in[9];
    const float* ln1b  = (const float*)d_in[10];
    const float* ln2g  = (const float*)d_in[11];
    const float* ln2b  = (const float*)d_in[12];
    float* out = (float*)d_out;

    float *qkv, *ctx, *tmp, *hbuf, *ff;
    cudaGetSymbolAddress((void**)&qkv,  g_qkv);
    cudaGetSymbolAddress((void**)&ctx,  g_ctx);
    cudaGetSymbolAddress((void**)&tmp,  g_tmp);
    cudaGetSymbolAddress((void**)&hbuf, g_h);
    cudaGetSymbolAddress((void**)&ff,   g_ff);

    cudaFuncSetAttribute(attn_kernel,
                         cudaFuncAttributeMaxDynamicSharedMemorySize,
                         ATTN_SMEM_BYTES);

    dim3 blk(256);

    // 1. QKV projection
    gemm_tf32<0><<<dim3(3 * DM / 128, T / 128), blk>>>(src, in_w, in_b, qkv, T, 3 * DM, DM);
    // 2. window-local attention
    attn_kernel<<<dim3(NH, NWIN, BB), blk, ATTN_SMEM_BYTES>>>();
    // 3. output projection
    gemm_tf32<0><<<dim3(DM / 128, T / 128), blk>>>(ctx, ow, ob, tmp, T, DM, DM);
    // 4. h = LN(src + attn)
    add_ln_kernel<<<T, 256>>>(src, tmp, ln1g, ln1b, hbuf);
    // 5. ff = relu(h @ w1^T + b1)
    gemm_tf32<1><<<dim3(FF / 128, T / 128), blk>>>(hbuf, w1, b1, ff, T, FF, DM);
    // 6. tmp = ff @ w2^T + b2
    gemm_tf32<0><<<dim3(DM / 128, T / 128), blk>>>(ff, w2, b2, tmp, T, DM, FF);
    // 7. out = LN(h + ff_out)
    add_ln_kernel<<<T, 256>>>(hbuf, tmp, ln2g, ln2b, out);
}

// round 3
// speedup vs baseline: 4.0194x; 4.0194x over previous
#include <cuda_runtime.h>
#include <cuda_fp16.h>
#include <cstdint>

// ---------------------------------------------------------------------------
// MultiAttnLayer, sm_103 baseline-ISA path (no tcgen05 in this toolchain):
// fp16 mma.sync.m16n8k16 + ldmatrix + 3-stage cp.async pipeline.
// ---------------------------------------------------------------------------

constexpr int BB   = 4;
constexpr int SEQ  = 8192;
constexpr int DM   = 1024;
constexpr int NH   = 16;
constexpr int HD   = 64;
constexpr int WIN  = 128;
constexpr int NWIN = SEQ / WIN;
constexpr int FF   = 4096;
constexpr int T    = BB * SEQ;
constexpr float LN_EPS = 1e-5f;

// Scratch (device globals: allocation-free).
__device__ __half g_src_h[(size_t)T * DM];
__device__ __half g_win_h[3 * DM * DM];
__device__ __half g_wout_h[DM * DM];
__device__ __half g_w1_h[FF * DM];
__device__ __half g_w2_h[DM * FF];
__device__ __half g_qkv_h[(size_t)T * 3 * DM];
__device__ __half g_ctx_h[(size_t)T * DM];
__device__ __half g_h16[(size_t)T * DM];
__device__ __half g_ff_h[(size_t)T * FF];
__device__ float  g_h32[(size_t)T * DM];
__device__ float  g_tmp32[(size_t)T * DM];

// ========================= helpers =========================================
__device__ __forceinline__ uint32_t smem_u32(const void* p) {
    uint32_t a;
    asm("{ .reg .u64 t; cvta.to.shared.u64 t, %1; cvt.u32.u64 %0, t; }" : "=r"(a) : "l"(p));
    return a;
}
__device__ __forceinline__ void cp_async16(uint32_t dst, const void* src) {
    asm volatile("cp.async.cg.shared.global [%0], [%1], 16;" :: "r"(dst), "l"(src));
}
__device__ __forceinline__ void cp_commit() { asm volatile("cp.async.commit_group;"); }
template <int N> __device__ __forceinline__ void cp_wait() {
    asm volatile("cp.async.wait_group %0;" :: "n"(N));
}
#define LDSM_X4(r0, r1, r2, r3, addr)                                          \
    asm volatile("ldmatrix.sync.aligned.m8n8.x4.shared.b16 {%0,%1,%2,%3}, [%4];" \
        : "=r"(r0), "=r"(r1), "=r"(r2), "=r"(r3) : "r"(addr))
#define LDSM_X4_T(r0, r1, r2, r3, addr)                                        \
    asm volatile("ldmatrix.sync.aligned.m8n8.x4.trans.shared.b16 {%0,%1,%2,%3}, [%4];" \
        : "=r"(r0), "=r"(r1), "=r"(r2), "=r"(r3) : "r"(addr))

__device__ __forceinline__ void mma_f16(float c[4], const uint32_t a[4],
                                        uint32_t b0, uint32_t b1) {
    asm volatile(
        "mma.sync.aligned.m16n8k16.row.col.f32.f16.f16.f32 "
        "{%0,%1,%2,%3}, {%4,%5,%6,%7}, {%8,%9}, {%0,%1,%2,%3};\n"
        : "+f"(c[0]), "+f"(c[1]), "+f"(c[2]), "+f"(c[3])
        : "r"(a[0]), "r"(a[1]), "r"(a[2]), "r"(a[3]), "r"(b0), "r"(b1));
}

// ========================= fp16 GEMM =======================================
// C[M,N] = A[M,K] @ B[N,K]^T + bias[N].  A,B fp16; acc fp32.
// Tile 128x256, BK=64, 512 threads (16 warps as 4m x 4n, warp tile 32x64),
// 3-stage cp.async pipeline, padded smem rows (144B) for conflict-free ldmatrix.
constexpr int BM = 128, BN = 256, BK = 64, STAGES = 3;
constexpr int AROW = 144;                 // bytes per smem row (64 halves + 8 pad)
constexpr int A_ST = BM * AROW;           // 18432
constexpr int B_ST = BN * AROW;           // 36864
constexpr int ST   = A_ST + B_ST;         // 55296
constexpr int GEMM_SMEM = STAGES * ST;    // 165888

template <int OUT_HALF, int RELU>
__global__ __launch_bounds__(512, 1)
void gemm_h(const __half* __restrict__ A, const __half* __restrict__ B,
            const float* __restrict__ bias, void* __restrict__ Cout,
            int M, int N, int K)
{
    extern __shared__ char smraw[];
    const uint32_t sb = smem_u32(smraw);

    const int tid  = threadIdx.x;
    const int wid  = tid >> 5;
    const int lane = tid & 31;
    const int wm   = wid >> 2;           // 0..3
    const int wn   = wid & 3;            // 0..3
    const int bm   = blockIdx.y * BM;
    const int bn   = blockIdx.x * BN;

    float acc[2][8][4];
#pragma unroll
    for (int i = 0; i < 2; i++)
#pragma unroll
        for (int j = 0; j < 8; j++)
#pragma unroll
            for (int l = 0; l < 4; l++) acc[i][j][l] = 0.f;

    auto load_stage = [&](int s, int k0) {
        const uint32_t ab = sb + s * ST;
#pragma unroll
        for (int i = 0; i < 2; i++) {            // A: 128 rows x 8 chunks
            int id = tid + i * 512;
            int r  = id >> 3;
            int c  = id & 7;
            cp_async16(ab + r * AROW + c * 16, A + (size_t)(bm + r) * K + k0 + c * 8);
        }
        const uint32_t bb = ab + A_ST;
#pragma unroll
        for (int i = 0; i < 4; i++) {            // B: 256 rows x 8 chunks
            int id = tid + i * 512;
            int r  = id >> 3;
            int c  = id & 7;
            cp_async16(bb + r * AROW + c * 16, B + (size_t)(bn + r) * K + k0 + c * 8);
        }
    };

    const int NK = K / BK;
#pragma unroll
    for (int s = 0; s < STAGES - 1; s++) { load_stage(s, s * BK); cp_commit(); }

    // lane-dependent base offsets
    const uint32_t a_lane = (uint32_t)((lane & 15) * AROW + ((lane >> 4) * 8) * 2);
    const uint32_t b_lane = (uint32_t)(((lane & 7) + ((lane >> 4) & 1) * 8) * AROW +
                                       (((lane >> 3) & 1) * 8) * 2);

    for (int k = 0; k < NK; k++) {
        cp_wait<STAGES - 2>();
        __syncthreads();
        if (k + STAGES - 1 < NK) load_stage((k + STAGES - 1) % STAGES, (k + STAGES - 1) * BK);
        cp_commit();

        const uint32_t as = sb + (k % STAGES) * ST;
        const uint32_t bs = as + A_ST;
        const uint32_t a_base = as + wm * 32 * AROW + a_lane;
        const uint32_t b_base = bs + wn * 64 * AROW + b_lane;

#pragma unroll
        for (int ks = 0; ks < 4; ks++) {
            uint32_t a[2][4];
#pragma unroll
            for (int im = 0; im < 2; im++)
                LDSM_X4(a[im][0], a[im][1], a[im][2], a[im][3],
                        a_base + im * 16 * AROW + ks * 32);
            uint32_t bf[8][2];
#pragma unroll
            for (int p = 0; p < 4; p++) {
                uint32_t r0, r1, r2, r3;
                LDSM_X4(r0, r1, r2, r3, b_base + p * 16 * AROW + ks * 32);
                bf[2 * p][0] = r0; bf[2 * p][1] = r1;
                bf[2 * p + 1][0] = r2; bf[2 * p + 1][1] = r3;
            }
#pragma unroll
            for (int im = 0; im < 2; im++)
#pragma unroll
                for (int n = 0; n < 8; n++)
                    mma_f16(acc[im][n], a[im], bf[n][0], bf[n][1]);
        }
    }

    // Epilogue
#pragma unroll
    for (int im = 0; im < 2; im++) {
        const int row = bm + wm * 32 + im * 16 + (lane >> 2);
#pragma unroll
        for (int n = 0; n < 8; n++) {
            const int col = bn + wn * 64 + n * 8 + (lane & 3) * 2;
            const float b0 = bias[col], b1 = bias[col + 1];
            float v00 = acc[im][n][0] + b0, v01 = acc[im][n][1] + b1;
            float v10 = acc[im][n][2] + b0, v11 = acc[im][n][3] + b1;
            if (RELU) {
                v00 = fmaxf(v00, 0.f); v01 = fmaxf(v01, 0.f);
                v10 = fmaxf(v10, 0.f); v11 = fmaxf(v11, 0.f);
            }
            if (OUT_HALF) {
                __half2* C = (__half2*)Cout;
                C[((size_t)row * N + col) >> 1]       = __floats2half2_rn(v00, v01);
                C[((size_t)(row + 8) * N + col) >> 1] = __floats2half2_rn(v10, v11);
            } else {
                float* C = (float*)Cout;
                C[(size_t)row * N + col]           = v00;
                C[(size_t)row * N + col + 1]       = v01;
                C[(size_t)(row + 8) * N + col]     = v10;
                C[(size_t)(row + 8) * N + col + 1] = v11;
            }
        }
    }
}

// ===================== window-local attention (fp16) =======================
// One block (256 thr) per (head, window, batch). Q,K,V 128x64 fp16 in smem,
// scores fp32, probs fp16, all matmul via mma.sync m16n8k16.
constexpr int QKV_B = 128 * 144;                       // bytes per Q/K/V tile
constexpr int S_LDF = 132;                             // fp32 score row stride
constexpr int P_LDH = 136;                             // fp16 prob row stride
constexpr int OFF_S = 3 * QKV_B;                       // 55296
constexpr int OFF_P = OFF_S + 128 * S_LDF * 4;         // +67584 = 122880
constexpr int ATTN_SMEM = OFF_P + 128 * P_LDH * 2;     // +34816 = 157696

__global__ __launch_bounds__(256, 1)
void attn_h()
{
    extern __shared__ char smraw[];
    const uint32_t sb = smem_u32(smraw);
    const uint32_t qh = sb;
    const uint32_t kh = sb + QKV_B;
    const uint32_t vh = sb + 2 * QKV_B;
    float* Sf = (float*)(smraw + OFF_S);
    __half* Ph = (__half*)(smraw + OFF_P);

    const int h  = blockIdx.x;
    const int w  = blockIdx.y;
    const int b  = blockIdx.z;
    const int t0 = b * SEQ + w * WIN;

    const int tid  = threadIdx.x;
    const int wid  = tid >> 5;
    const int lane = tid & 31;

    // Load Q,K,V tiles (each 128 rows x 64 halves = 8 x 16B chunks per row)
    const __half* qkv = g_qkv_h;
#pragma unroll
    for (int i = 0; i < 4; i++) {
        int id = tid + i * 256;          // 0..1023
        int r  = id >> 3;
        int c  = id & 7;
        const __half* base = qkv + (size_t)(t0 + r) * (3 * DM) + h * HD + c * 8;
        uint32_t doff = r * 144 + c * 16;
        cp_async16(qh + doff, base);
        cp_async16(kh + doff, base + DM);
        cp_async16(vh + doff, base + 2 * DM);
    }
    cp_commit();
    cp_wait<0>();
    __syncthreads();

    const int m0 = wid * 16;

    // ---- scores = Q @ K^T (per warp: 16 x 128, K-dim 64) ----
    float sc[16][4];
#pragma unroll
    for (int n = 0; n < 16; n++)
#pragma unroll
        for (int l = 0; l < 4; l++) sc[n][l] = 0.f;

    const uint32_t a_base = qh + (m0 + (lane & 15)) * 144 + ((lane >> 4) * 8) * 2;
    const uint32_t k_base = kh + ((lane & 7) + ((lane >> 4) & 1) * 8) * 144 +
                            (((lane >> 3) & 1) * 8) * 2;
#pragma unroll
    for (int ks = 0; ks < 4; ks++) {
        uint32_t a[4];
        LDSM_X4(a[0], a[1], a[2], a[3], a_base + ks * 32);
#pragma unroll
        for (int p = 0; p < 8; p++) {
            uint32_t r0, r1, r2, r3;
            LDSM_X4(r0, r1, r2, r3, k_base + p * 16 * 144 + ks * 32);
            mma_f16(sc[2 * p], a, r0, r1);
            mma_f16(sc[2 * p + 1], a, r2, r3);
        }
    }

    const float scale = 0.125f;   // 1/sqrt(64)
    {
        const int r = m0 + (lane >> 2);
#pragma unroll
        for (int n = 0; n < 16; n++) {
            const int c = n * 8 + (lane & 3) * 2;
            Sf[r * S_LDF + c]           = sc[n][0] * scale;
            Sf[r * S_LDF + c + 1]       = sc[n][1] * scale;
            Sf[(r + 8) * S_LDF + c]     = sc[n][2] * scale;
            Sf[(r + 8) * S_LDF + c + 1] = sc[n][3] * scale;
        }
    }
    __syncthreads();

    // ---- softmax (1 thread per row, fp32) -> probs fp16 ----
    if (tid < WIN) {
        float* row = Sf + tid * S_LDF;
        __half* prow = Ph + tid * P_LDH;
        float m = -1e30f;
#pragma unroll 4
        for (int i = 0; i < WIN; i++) m = fmaxf(m, row[i]);
        float s = 0.f;
        float e[WIN / 4][4];
#pragma unroll 4
        for (int i = 0; i < WIN; i++) {
            float v = __expf(row[i] - m);
            e[i >> 2][i & 3] = v;
            s += v;
        }
        const float inv = 1.f / s;
#pragma unroll 4
        for (int i = 0; i < WIN; i++)
            prow[i] = __float2half(e[i >> 2][i & 3] * inv);
    }
    __syncthreads();

    // ---- ctx = P @ V (per warp: 16 x 64, K-dim 128) ----
    float o[8][4];
#pragma unroll
    for (int n = 0; n < 8; n++)
#pragma unroll
        for (int l = 0; l < 4; l++) o[n][l] = 0.f;

    const uint32_t p_base = (uint32_t)(OFF_P + (m0 + (lane & 15)) * P_LDH * 2 +
                                       ((lane >> 4) * 8) * 2) + sb;
    const uint32_t v_base = vh + ((lane & 7) + ((lane >> 3) & 1) * 8) * 144 +
                            ((lane >> 4) * 8) * 2;
#pragma unroll
    for (int ks = 0; ks < 8; ks++) {
        uint32_t a[4];
        LDSM_X4(a[0], a[1], a[2], a[3], p_base + ks * 32);
#pragma unroll
        for (int p = 0; p < 4; p++) {
            uint32_t r0, r1, r2, r3;
            LDSM_X4_T(r0, r1, r2, r3, v_base + ks * 16 * 144 + p * 32);
            mma_f16(o[2 * p], a, r0, r1);
            mma_f16(o[2 * p + 1], a, r2, r3);
        }
    }

    // store ctx (fp16)
    {
        const int r = m0 + (lane >> 2);
#pragma unroll
        for (int n = 0; n < 8; n++) {
            const int c = h * HD + n * 8 + (lane & 3) * 2;
            __half2* o0 = (__half2*)(g_ctx_h + (size_t)(t0 + r) * DM + c);
            __half2* o1 = (__half2*)(g_ctx_h + (size_t)(t0 + r + 8) * DM + c);
            *o0 = __floats2half2_rn(o[n][0], o[n][1]);
            *o1 = __floats2half2_rn(o[n][2], o[n][3]);
        }
    }
}

// ============================ add + LayerNorm ==============================
__global__ __launch_bounds__(256)
void add_ln_kernel(const float* __restrict__ A, const float* __restrict__ Bq,
                   const float* __restrict__ gam, const float* __restrict__ bet,
                   float* __restrict__ out, __half* __restrict__ out16)
{
    const int t    = blockIdx.x;
    const int tid  = threadIdx.x;
    const int lane = tid & 31;
    const int wid  = tid >> 5;

    const size_t base = (size_t)t * DM + tid * 4;
    float4 a  = *(const float4*)(A  + base);
    float4 bb = *(const float4*)(Bq + base);
    float x0 = a.x + bb.x, x1 = a.y + bb.y, x2 = a.z + bb.z, x3 = a.w + bb.w;

    float s = x0 + x1 + x2 + x3;
    float q = x0 * x0 + x1 * x1 + x2 * x2 + x3 * x3;
#pragma unroll
    for (int o = 16; o > 0; o >>= 1) {
        s += __shfl_xor_sync(0xffffffffu, s, o);
        q += __shfl_xor_sync(0xffffffffu, q, o);
    }
    __shared__ float rs[8], rq[8];
    if (lane == 0) { rs[wid] = s; rq[wid] = q; }
    __syncthreads();
    if (wid == 0) {
        s = (lane < 8) ? rs[lane] : 0.f;
        q = (lane < 8) ? rq[lane] : 0.f;
#pragma unroll
        for (int o = 4; o > 0; o >>= 1) {
            s += __shfl_xor_sync(0xffffffffu, s, o);
            q += __shfl_xor_sync(0xffffffffu, q, o);
        }
        if (lane == 0) { rs[0] = s; rq[0] = q; }
    }
    __syncthreads();
    const float mu   = rs[0] * (1.f / DM);
    const float var  = rq[0] * (1.f / DM) - mu * mu;
    const float rstd = rsqrtf(var + LN_EPS);

    float4 gv = *(const float4*)(gam + tid * 4);
    float4 bv = *(const float4*)(bet + tid * 4);
    float4 r;
    r.x = (x0 - mu) * rstd * gv.x + bv.x;
    r.y = (x1 - mu) * rstd * gv.y + bv.y;
    r.z = (x2 - mu) * rstd * gv.z + bv.z;
    r.w = (x3 - mu) * rstd * gv.w + bv.w;
    *(float4*)(out + base) = r;
    if (out16) {
        *(__half2*)(out16 + base)     = __floats2half2_rn(r.x, r.y);
        *(__half2*)(out16 + base + 2) = __floats2half2_rn(r.z, r.w);
    }
}

// ======================= fp32 -> fp16 convert ==============================
__global__ __launch_bounds__(256)
void cvt_f2h(const float* __restrict__ in, __half* __restrict__ out, int n)
{
    int i = (blockIdx.x * 256 + threadIdx.x) * 4;
    if (i < n) {
        float4 v = *(const float4*)(in + i);
        *(__half2*)(out + i)     = __floats2half2_rn(v.x, v.y);
        *(__half2*)(out + i + 2) = __floats2half2_rn(v.z, v.w);
    }
}

// ---------------------------------------------------------------------------
extern "C" void kernel_launch(void* const* d_in, const int* in_sizes, int n_in,
                              void* d_out, int out_size)
{
    const float* src   = (const float*)d_in[0];
    const float* in_w  = (const float*)d_in[1];
    const float* in_b  = (const float*)d_in[2];
    const float* ow    = (const float*)d_in[3];
    const float* ob    = (const float*)d_in[4];
    const float* w1    = (const float*)d_in[5];
    const float* b1    = (const float*)d_in[6];
    const float* w2    = (const float*)d_in[7];
    const float* b2    = (const float*)d_in[8];
    const float* ln1g  = (const float*)d_in[9];
    const float* ln1b  = (const float*)d_in[10];
    const float* ln2g  = (const float*)d_in[11];
    const float* ln2b  = (const float*)d_in[12];
    float* out = (float*)d_out;

    __half *src_h, *win_h, *wout_h, *w1_h, *w2_h, *qkv_h, *ctx_h, *h16, *ff_h;
    float *h32, *tmp32;
    cudaGetSymbolAddress((void**)&src_h,  g_src_h);
    cudaGetSymbolAddress((void**)&win_h,  g_win_h);
    cudaGetSymbolAddress((void**)&wout_h, g_wout_h);
    cudaGetSymbolAddress((void**)&w1_h,   g_w1_h);
    cudaGetSymbolAddress((void**)&w2_h,   g_w2_h);
    cudaGetSymbolAddress((void**)&qkv_h,  g_qkv_h);
    cudaGetSymbolAddress((void**)&ctx_h,  g_ctx_h);
    cudaGetSymbolAddress((void**)&h16,    g_h16);
    cudaGetSymbolAddress((void**)&ff_h,   g_ff_h);
    cudaGetSymbolAddress((void**)&h32,    g_h32);
    cudaGetSymbolAddress((void**)&tmp32,  g_tmp32);

    cudaFuncSetAttribute(gemm_h<0, 0>, cudaFuncAttributeMaxDynamicSharedMemorySize, GEMM_SMEM);
    cudaFuncSetAttribute(gemm_h<1, 0>, cudaFuncAttributeMaxDynamicSharedMemorySize, GEMM_SMEM);
    cudaFuncSetAttribute(gemm_h<1, 1>, cudaFuncAttributeMaxDynamicSharedMemorySize, GEMM_SMEM);
    cudaFuncSetAttribute(attn_h, cudaFuncAttributeMaxDynamicSharedMemorySize, ATTN_SMEM);

    // Convert inputs to fp16
    cvt_f2h<<<(T * DM / 4 + 255) / 256, 256>>>(src, src_h, T * DM);
    cvt_f2h<<<(3 * DM * DM / 4 + 255) / 256, 256>>>(in_w, win_h, 3 * DM * DM);
    cvt_f2h<<<(DM * DM / 4 + 255) / 256, 256>>>(ow, wout_h, DM * DM);
    cvt_f2h<<<(FF * DM / 4 + 255) / 256, 256>>>(w1, w1_h, FF * DM);
    cvt_f2h<<<(DM * FF / 4 + 255) / 256, 256>>>(w2, w2_h, DM * FF);

    dim3 blk512(512);

    // 1. qkv = src @ in_w^T + b  (fp16 out)
    gemm_h<1, 0><<<dim3(3 * DM / BN, T / BM), blk512, GEMM_SMEM>>>(
        src_h, win_h, in_b, qkv_h, T, 3 * DM, DM);
    // 2. window-local attention -> ctx fp16
    attn_h<<<dim3(NH, NWIN, BB), 256, ATTN_SMEM>>>();
    // 3. tmp = ctx @ out_w^T + b (fp32 out)
    gemm_h<0, 0><<<dim3(DM / BN, T / BM), blk512, GEMM_SMEM>>>(
        ctx_h, wout_h, ob, tmp32, T, DM, DM);
    // 4. h = LN(src + tmp)  (fp32 + fp16 copies)
    add_ln_kernel<<<T, 256>>>(src, tmp32, ln1g, ln1b, h32, h16);
    // 5. ff = relu(h @ w1^T + b1) (fp16 out)
    gemm_h<1, 1><<<dim3(FF / BN, T / BM), blk512, GEMM_SMEM>>>(
        h16, w1_h, b1, ff_h, T, FF, DM);
    // 6. tmp = ff @ w2^T + b2 (fp32 out)
    gemm_h<0, 0><<<dim3(DM / BN, T / BM), blk512, GEMM_SMEM>>>(
        ff_h, w2_h, b2, tmp32, T, DM, FF);
    // 7. out = LN(h + tmp)
    add_ln_kernel<<<T, 256>>>(h32, tmp32, ln2g, ln2b, out, nullptr);
}

// round 4
// speedup vs baseline: 4.4213x; 1.1000x over previous
#include <cuda_runtime.h>
#include <cuda_fp16.h>
#include <cstdint>

// ---------------------------------------------------------------------------
// MultiAttnLayer, sm_103 baseline-ISA path: fp16 mma.sync.m16n8k16 + ldmatrix
// + cp.async. 2-CTA/SM GEMM (128x128 tile), register-softmax attention,
// residual fused into GEMM epilogues.
// ---------------------------------------------------------------------------

constexpr int BB   = 4;
constexpr int SEQ  = 8192;
constexpr int DM   = 1024;
constexpr int NH   = 16;
constexpr int HD   = 64;
constexpr int WIN  = 128;
constexpr int NWIN = SEQ / WIN;
constexpr int FF   = 4096;
constexpr int T    = BB * SEQ;
constexpr float LN_EPS = 1e-5f;

// Scratch (device globals: allocation-free).
__device__ __half g_src_h[(size_t)T * DM];
__device__ __half g_win_h[3 * DM * DM];
__device__ __half g_wout_h[DM * DM];
__device__ __half g_w1_h[FF * DM];
__device__ __half g_w2_h[DM * FF];
__device__ __half g_qkv_h[(size_t)T * 3 * DM];
__device__ __half g_ctx_h[(size_t)T * DM];
__device__ __half g_h16[(size_t)T * DM];
__device__ __half g_ff_h[(size_t)T * FF];
__device__ float  g_h32[(size_t)T * DM];
__device__ float  g_x32[(size_t)T * DM];

// ========================= helpers =========================================
__device__ __forceinline__ uint32_t smem_u32(const void* p) {
    uint32_t a;
    asm("{ .reg .u64 t; cvta.to.shared.u64 t, %1; cvt.u32.u64 %0, t; }" : "=r"(a) : "l"(p));
    return a;
}
__device__ __forceinline__ void cp_async16(uint32_t dst, const void* src) {
    asm volatile("cp.async.cg.shared.global [%0], [%1], 16;" :: "r"(dst), "l"(src));
}
__device__ __forceinline__ void cp_commit() { asm volatile("cp.async.commit_group;"); }
template <int N> __device__ __forceinline__ void cp_wait() {
    asm volatile("cp.async.wait_group %0;" :: "n"(N));
}
#define LDSM_X4(r0, r1, r2, r3, addr)                                          \
    asm volatile("ldmatrix.sync.aligned.m8n8.x4.shared.b16 {%0,%1,%2,%3}, [%4];" \
        : "=r"(r0), "=r"(r1), "=r"(r2), "=r"(r3) : "r"(addr))
#define LDSM_X4_T(r0, r1, r2, r3, addr)                                        \
    asm volatile("ldmatrix.sync.aligned.m8n8.x4.trans.shared.b16 {%0,%1,%2,%3}, [%4];" \
        : "=r"(r0), "=r"(r1), "=r"(r2), "=r"(r3) : "r"(addr))

__device__ __forceinline__ void mma_f16(float c[4], const uint32_t a[4],
                                        uint32_t b0, uint32_t b1) {
    asm volatile(
        "mma.sync.aligned.m16n8k16.row.col.f32.f16.f16.f32 "
        "{%0,%1,%2,%3}, {%4,%5,%6,%7}, {%8,%9}, {%0,%1,%2,%3};\n"
        : "+f"(c[0]), "+f"(c[1]), "+f"(c[2]), "+f"(c[3])
        : "r"(a[0]), "r"(a[1]), "r"(a[2]), "r"(a[3]), "r"(b0), "r"(b1));
}

// ========================= fp16 GEMM =======================================
// C[M,N] = A[M,K] @ B[N,K]^T + bias[N] (+ residual).  A,B fp16; acc fp32.
// Tile 128x128, BK=64, 256 threads (8 warps, 4m x 2n, warp tile 32x64),
// 3-stage cp.async, 2 CTAs/SM.
constexpr int BM = 128, BN = 128, BK = 64, STAGES = 3;
constexpr int AROW = 144;                 // 64 halves + 8 pad
constexpr int A_ST = BM * AROW;           // 18432
constexpr int B_ST = BN * AROW;           // 18432
constexpr int ST   = A_ST + B_ST;         // 36864
constexpr int GEMM_SMEM = STAGES * ST;    // 110592

template <int OUT_HALF, int RELU, int RES>
__global__ __launch_bounds__(256, 2)
void gemm_h(const __half* __restrict__ A, const __half* __restrict__ B,
            const float* __restrict__ bias, const float* __restrict__ Res,
            void* __restrict__ Cout, int M, int N, int K)
{
    extern __shared__ char smraw[];
    const uint32_t sb = smem_u32(smraw);

    const int tid  = threadIdx.x;
    const int wid  = tid >> 5;
    const int lane = tid & 31;
    const int wm   = wid >> 1;           // 0..3
    const int wn   = wid & 1;            // 0..1
    const int bm   = blockIdx.y * BM;
    const int bn   = blockIdx.x * BN;

    float acc[2][8][4];
#pragma unroll
    for (int i = 0; i < 2; i++)
#pragma unroll
        for (int j = 0; j < 8; j++)
#pragma unroll
            for (int l = 0; l < 4; l++) acc[i][j][l] = 0.f;

    auto load_stage = [&](int s, int k0) {
        const uint32_t ab = sb + s * ST;
#pragma unroll
        for (int i = 0; i < 4; i++) {            // A: 128 rows x 8 chunks(16B)
            int id = tid + i * 256;
            int r  = id >> 3;
            int c  = id & 7;
            cp_async16(ab + r * AROW + c * 16, A + (size_t)(bm + r) * K + k0 + c * 8);
        }
        const uint32_t bb = ab + A_ST;
#pragma unroll
        for (int i = 0; i < 4; i++) {            // B: 128 rows x 8 chunks
            int id = tid + i * 256;
            int r  = id >> 3;
            int c  = id & 7;
            cp_async16(bb + r * AROW + c * 16, B + (size_t)(bn + r) * K + k0 + c * 8);
        }
    };

    const int NK = K / BK;
#pragma unroll
    for (int s = 0; s < STAGES - 1; s++) { load_stage(s, s * BK); cp_commit(); }

    const uint32_t a_lane = (uint32_t)((lane & 15) * AROW + (lane >> 4) * 16);
    const uint32_t b_lane = (uint32_t)(((lane & 7) + ((lane >> 4) & 1) * 8) * AROW +
                                       ((lane >> 3) & 1) * 16);

    for (int k = 0; k < NK; k++) {
        cp_wait<STAGES - 2>();
        __syncthreads();
        if (k + STAGES - 1 < NK) load_stage((k + STAGES - 1) % STAGES, (k + STAGES - 1) * BK);
        cp_commit();

        const uint32_t as = sb + (k % STAGES) * ST;
        const uint32_t bs = as + A_ST;
        const uint32_t a_base = as + wm * 32 * AROW + a_lane;
        const uint32_t b_base = bs + wn * 64 * AROW + b_lane;

#pragma unroll
        for (int ks = 0; ks < 4; ks++) {
            uint32_t a[2][4];
#pragma unroll
            for (int im = 0; im < 2; im++)
                LDSM_X4(a[im][0], a[im][1], a[im][2], a[im][3],
                        a_base + im * 16 * AROW + ks * 32);
            uint32_t bf[8][2];
#pragma unroll
            for (int p = 0; p < 4; p++) {
                uint32_t r0, r1, r2, r3;
                LDSM_X4(r0, r1, r2, r3, b_base + p * 16 * AROW + ks * 32);
                bf[2 * p][0] = r0; bf[2 * p][1] = r1;
                bf[2 * p + 1][0] = r2; bf[2 * p + 1][1] = r3;
            }
#pragma unroll
            for (int im = 0; im < 2; im++)
#pragma unroll
                for (int n = 0; n < 8; n++)
                    mma_f16(acc[im][n], a[im], bf[n][0], bf[n][1]);
        }
    }

    // Epilogue
#pragma unroll
    for (int im = 0; im < 2; im++) {
        const int row = bm + wm * 32 + im * 16 + (lane >> 2);
#pragma unroll
        for (int n = 0; n < 8; n++) {
            const int col = bn + wn * 64 + n * 8 + (lane & 3) * 2;
            const float b0 = bias[col], b1 = bias[col + 1];
            float v00 = acc[im][n][0] + b0, v01 = acc[im][n][1] + b1;
            float v10 = acc[im][n][2] + b0, v11 = acc[im][n][3] + b1;
            if (RES) {
                const size_t i0 = (size_t)row * N + col;
                const size_t i1 = (size_t)(row + 8) * N + col;
                v00 += Res[i0]; v01 += Res[i0 + 1];
                v10 += Res[i1]; v11 += Res[i1 + 1];
            }
            if (RELU) {
                v00 = fmaxf(v00, 0.f); v01 = fmaxf(v01, 0.f);
                v10 = fmaxf(v10, 0.f); v11 = fmaxf(v11, 0.f);
            }
            if (OUT_HALF) {
                __half2* C = (__half2*)Cout;
                C[((size_t)row * N + col) >> 1]       = __floats2half2_rn(v00, v01);
                C[((size_t)(row + 8) * N + col) >> 1] = __floats2half2_rn(v10, v11);
            } else {
                float* C = (float*)Cout;
                C[(size_t)row * N + col]           = v00;
                C[(size_t)row * N + col + 1]       = v01;
                C[(size_t)(row + 8) * N + col]     = v10;
                C[(size_t)(row + 8) * N + col + 1] = v11;
            }
        }
    }
}

// ===================== window-local attention (fp16) =======================
// One block (256 thr) per (head, window, batch); register softmax; 2 CTA/SM.
constexpr int QKV_B  = 128 * 144;                 // bytes per Q/K/V tile
constexpr int P_ROWB = 272;                       // fp16 prob row bytes (136 halves)
constexpr int OFF_P  = 3 * QKV_B;                 // 55296
constexpr int ATTN_SMEM = OFF_P + 128 * P_ROWB;   // 90112

__global__ __launch_bounds__(256, 2)
void attn_h()
{
    extern __shared__ char smraw[];
    const uint32_t sb = smem_u32(smraw);
    const uint32_t qh = sb;
    const uint32_t kh = sb + QKV_B;
    const uint32_t vh = sb + 2 * QKV_B;
    __half* Ph = (__half*)(smraw + OFF_P);

    const int h  = blockIdx.x;
    const int w  = blockIdx.y;
    const int b  = blockIdx.z;
    const int t0 = b * SEQ + w * WIN;

    const int tid  = threadIdx.x;
    const int wid  = tid >> 5;
    const int lane = tid & 31;
    const int gid  = lane >> 2;
    const int tig  = lane & 3;

#pragma unroll
    for (int i = 0; i < 4; i++) {
        int id = tid + i * 256;
        int r  = id >> 3;
        int c  = id & 7;
        const __half* base = g_qkv_h + (size_t)(t0 + r) * (3 * DM) + h * HD + c * 8;
        uint32_t doff = r * 144 + c * 16;
        cp_async16(qh + doff, base);
        cp_async16(kh + doff, base + DM);
        cp_async16(vh + doff, base + 2 * DM);
    }
    cp_commit();
    cp_wait<0>();
    __syncthreads();

    const int m0 = wid * 16;

    // ---- scores = Q @ K^T (per warp: 16 x 128, K-dim 64) ----
    float sc[16][4];
#pragma unroll
    for (int n = 0; n < 16; n++)
#pragma unroll
        for (int l = 0; l < 4; l++) sc[n][l] = 0.f;

    const uint32_t a_base = qh + (m0 + (lane & 15)) * 144 + (lane >> 4) * 16;
    const uint32_t k_base = kh + ((lane & 7) + ((lane >> 4) & 1) * 8) * 144 +
                            ((lane >> 3) & 1) * 16;
#pragma unroll
    for (int ks = 0; ks < 4; ks++) {
        uint32_t a[4];
        LDSM_X4(a[0], a[1], a[2], a[3], a_base + ks * 32);
#pragma unroll
        for (int p = 0; p < 8; p++) {
            uint32_t r0, r1, r2, r3;
            LDSM_X4(r0, r1, r2, r3, k_base + p * 16 * 144 + ks * 32);
            mma_f16(sc[2 * p], a, r0, r1);
            mma_f16(sc[2 * p + 1], a, r2, r3);
        }
    }

    // ---- softmax in registers ----
    // Row A = m0+gid holds sc[n][0..1]; row B = m0+8+gid holds sc[n][2..3].
    // Each row is spread over the 4 threads of a quad (tig 0..3).
    const float scale = 0.125f;
    float mA = -1e30f, mB = -1e30f;
#pragma unroll
    for (int n = 0; n < 16; n++) {
#pragma unroll
        for (int l = 0; l < 4; l++) sc[n][l] *= scale;
        mA = fmaxf(mA, fmaxf(sc[n][0], sc[n][1]));
        mB = fmaxf(mB, fmaxf(sc[n][2], sc[n][3]));
    }
    mA = fmaxf(mA, __shfl_xor_sync(0xffffffffu, mA, 1));
    mA = fmaxf(mA, __shfl_xor_sync(0xffffffffu, mA, 2));
    mB = fmaxf(mB, __shfl_xor_sync(0xffffffffu, mB, 1));
    mB = fmaxf(mB, __shfl_xor_sync(0xffffffffu, mB, 2));

    float sA = 0.f, sB = 0.f;
#pragma unroll
    for (int n = 0; n < 16; n++) {
        sc[n][0] = __expf(sc[n][0] - mA);
        sc[n][1] = __expf(sc[n][1] - mA);
        sc[n][2] = __expf(sc[n][2] - mB);
        sc[n][3] = __expf(sc[n][3] - mB);
        sA += sc[n][0] + sc[n][1];
        sB += sc[n][2] + sc[n][3];
    }
    sA += __shfl_xor_sync(0xffffffffu, sA, 1);
    sA += __shfl_xor_sync(0xffffffffu, sA, 2);
    sB += __shfl_xor_sync(0xffffffffu, sB, 1);
    sB += __shfl_xor_sync(0xffffffffu, sB, 2);
    const float invA = 1.f / sA, invB = 1.f / sB;

    {
        const int rA = m0 + gid;
        __half2* pA = (__half2*)(smraw + OFF_P + rA * P_ROWB);
        __half2* pB = (__half2*)(smraw + OFF_P + (rA + 8) * P_ROWB);
#pragma unroll
        for (int n = 0; n < 16; n++) {
            const int c2 = (n * 8 + tig * 2) >> 1;   // half2 index
            pA[c2] = __floats2half2_rn(sc[n][0] * invA, sc[n][1] * invA);
            pB[c2] = __floats2half2_rn(sc[n][2] * invB, sc[n][3] * invB);
        }
    }
    __syncthreads();

    // ---- ctx = P @ V (per warp: 16 x 64, K-dim 128) ----
    float o[8][4];
#pragma unroll
    for (int n = 0; n < 8; n++)
#pragma unroll
        for (int l = 0; l < 4; l++) o[n][l] = 0.f;

    const uint32_t p_base = sb + OFF_P + (m0 + (lane & 15)) * P_ROWB + (lane >> 4) * 16;
    const uint32_t v_base = vh + ((lane & 7) + ((lane >> 3) & 1) * 8) * 144 +
                            (lane >> 4) * 16;
#pragma unroll
    for (int ks = 0; ks < 8; ks++) {
        uint32_t a[4];
        LDSM_X4(a[0], a[1], a[2], a[3], p_base + ks * 32);
#pragma unroll
        for (int p = 0; p < 4; p++) {
            uint32_t r0, r1, r2, r3;
            LDSM_X4_T(r0, r1, r2, r3, v_base + ks * 16 * 144 + p * 32);
            mma_f16(o[2 * p], a, r0, r1);
            mma_f16(o[2 * p + 1], a, r2, r3);
        }
    }

    {
        const int r = m0 + gid;
#pragma unroll
        for (int n = 0; n < 8; n++) {
            const int c = h * HD + n * 8 + tig * 2;
            __half2* o0 = (__half2*)(g_ctx_h + (size_t)(t0 + r) * DM + c);
            __half2* o1 = (__half2*)(g_ctx_h + (size_t)(t0 + r + 8) * DM + c);
            *o0 = __floats2half2_rn(o[n][0], o[n][1]);
            *o1 = __floats2half2_rn(o[n][2], o[n][3]);
        }
    }
}

// ============================ LayerNorm ====================================
__global__ __launch_bounds__(256)
void ln_kernel(const float* __restrict__ X,
               const float* __restrict__ gam, const float* __restrict__ bet,
               float* __restrict__ out, __half* __restrict__ out16)
{
    const int t    = blockIdx.x;
    const int tid  = threadIdx.x;
    const int lane = tid & 31;
    const int wid  = tid >> 5;

    const size_t base = (size_t)t * DM + tid * 4;
    float4 a = *(const float4*)(X + base);
    float x0 = a.x, x1 = a.y, x2 = a.z, x3 = a.w;

    float s = x0 + x1 + x2 + x3;
    float q = x0 * x0 + x1 * x1 + x2 * x2 + x3 * x3;
#pragma unroll
    for (int o = 16; o > 0; o >>= 1) {
        s += __shfl_xor_sync(0xffffffffu, s, o);
        q += __shfl_xor_sync(0xffffffffu, q, o);
    }
    __shared__ float rs[8], rq[8];
    if (lane == 0) { rs[wid] = s; rq[wid] = q; }
    __syncthreads();
    if (wid == 0) {
        s = (lane < 8) ? rs[lane] : 0.f;
        q = (lane < 8) ? rq[lane] : 0.f;
#pragma unroll
        for (int o = 4; o > 0; o >>= 1) {
            s += __shfl_xor_sync(0xffffffffu, s, o);
            q += __shfl_xor_sync(0xffffffffu, q, o);
        }
        if (lane == 0) { rs[0] = s; rq[0] = q; }
    }
    __syncthreads();
    const float mu   = rs[0] * (1.f / DM);
    const float var  = rq[0] * (1.f / DM) - mu * mu;
    const float rstd = rsqrtf(var + LN_EPS);

    float4 gv = *(const float4*)(gam + tid * 4);
    float4 bv = *(const float4*)(bet + tid * 4);
    float4 r;
    r.x = (x0 - mu) * rstd * gv.x + bv.x;
    r.y = (x1 - mu) * rstd * gv.y + bv.y;
    r.z = (x2 - mu) * rstd * gv.z + bv.z;
    r.w = (x3 - mu) * rstd * gv.w + bv.w;
    *(float4*)(out + base) = r;
    if (out16) {
        *(__half2*)(out16 + base)     = __floats2half2_rn(r.x, r.y);
        *(__half2*)(out16 + base + 2) = __floats2half2_rn(r.z, r.w);
    }
}

// ======================= fp32 -> fp16 convert ==============================
__global__ __launch_bounds__(256)
void cvt_f2h(const float* __restrict__ in, __half* __restrict__ out, int n)
{
    int i = (blockIdx.x * 256 + threadIdx.x) * 4;
    if (i < n) {
        float4 v = *(const float4*)(in + i);
        *(__half2*)(out + i)     = __floats2half2_rn(v.x, v.y);
        *(__half2*)(out + i + 2) = __floats2half2_rn(v.z, v.w);
    }
}

// ---------------------------------------------------------------------------
extern "C" void kernel_launch(void* const* d_in, const int* in_sizes, int n_in,
                              void* d_out, int out_size)
{
    const float* src   = (const float*)d_in[0];
    const float* in_w  = (const float*)d_in[1];
    const float* in_b  = (const float*)d_in[2];
    const float* ow    = (const float*)d_in[3];
    const float* ob    = (const float*)d_in[4];
    const float* w1    = (const float*)d_in[5];
    const float* b1    = (const float*)d_in[6];
    const float* w2    = (const float*)d_in[7];
    const float* b2    = (const float*)d_in[8];
    const float* ln1g  = (const float*)d_in[9];
    const float* ln1b  = (const float*)d_in[10];
    const float* ln2g  = (const float*)d_in[11];
    const float* ln2b  = (const float*)d_in[12];
    float* out = (float*)d_out;

    __half *src_h, *win_h, *wout_h, *w1_h, *w2_h, *qkv_h, *ctx_h, *h16, *ff_h;
    float *h32, *x32;
    cudaGetSymbolAddress((void**)&src_h,  g_src_h);
    cudaGetSymbolAddress((void**)&win_h,  g_win_h);
    cudaGetSymbolAddress((void**)&wout_h, g_wout_h);
    cudaGetSymbolAddress((void**)&w1_h,   g_w1_h);
    cudaGetSymbolAddress((void**)&w2_h,   g_w2_h);
    cudaGetSymbolAddress((void**)&qkv_h,  g_qkv_h);
    cudaGetSymbolAddress((void**)&ctx_h,  g_ctx_h);
    cudaGetSymbolAddress((void**)&h16,    g_h16);
    cudaGetSymbolAddress((void**)&ff_h,   g_ff_h);
    cudaGetSymbolAddress((void**)&h32,    g_h32);
    cudaGetSymbolAddress((void**)&x32,    g_x32);

    cudaFuncSetAttribute(gemm_h<1, 0, 0>, cudaFuncAttributeMaxDynamicSharedMemorySize, GEMM_SMEM);
    cudaFuncSetAttribute(gemm_h<0, 0, 1>, cudaFuncAttributeMaxDynamicSharedMemorySize, GEMM_SMEM);
    cudaFuncSetAttribute(gemm_h<1, 1, 0>, cudaFuncAttributeMaxDynamicSharedMemorySize, GEMM_SMEM);
    cudaFuncSetAttribute(attn_h, cudaFuncAttributeMaxDynamicSharedMemorySize, ATTN_SMEM);

    // Convert inputs to fp16
    cvt_f2h<<<(T * DM / 4 + 255) / 256, 256>>>(src, src_h, T * DM);
    cvt_f2h<<<(3 * DM * DM / 4 + 255) / 256, 256>>>(in_w, win_h, 3 * DM * DM);
    cvt_f2h<<<(DM * DM / 4 + 255) / 256, 256>>>(ow, wout_h, DM * DM);
    cvt_f2h<<<(FF * DM / 4 + 255) / 256, 256>>>(w1, w1_h, FF * DM);
    cvt_f2h<<<(DM * FF / 4 + 255) / 256, 256>>>(w2, w2_h, DM * FF);

    // 1. qkv = src @ in_w^T + b (fp16 out)
    gemm_h<1, 0, 0><<<dim3(3 * DM / BN, T / BM), 256, GEMM_SMEM>>>(
        src_h, win_h, in_b, nullptr, qkv_h, T, 3 * DM, DM);
    // 2. window-local attention -> ctx fp16
    attn_h<<<dim3(NH, NWIN, BB), 256, ATTN_SMEM>>>();
    // 3. x = ctx @ ow^T + ob + src (fp32 out, residual fused)
    gemm_h<0, 0, 1><<<dim3(DM / BN, T / BM), 256, GEMM_SMEM>>>(
        ctx_h, wout_h, ob, src, x32, T, DM, DM);
    // 4. h = LN(x)
    ln_kernel<<<T, 256>>>(x32, ln1g, ln1b, h32, h16);
    // 5. ff = relu(h @ w1^T + b1) (fp16 out)
    gemm_h<1, 1, 0><<<dim3(FF / BN, T / BM), 256, GEMM_SMEM>>>(
        h16, w1_h, b1, nullptr, ff_h, T, FF, DM);
    // 6. x = ff @ w2^T + b2 + h (fp32 out, residual fused)
    gemm_h<0, 0, 1><<<dim3(DM / BN, T / BM), 256, GEMM_SMEM>>>(
        ff_h, w2_h, b2, h32, x32, T, DM, FF);
    // 7. out = LN(x)
    ln_kernel<<<T, 256>>>(x32, ln2g, ln2b, out, nullptr);
}